// round 10
// baseline (speedup 1.0000x reference)
#include <cuda_runtime.h>
#include <cuda_fp16.h>
#include <cstdint>

#define B_ 8192
#define D_ 4096
#define H_ 2048
#define K_ 512
#define LN_EPS 1e-5f

// ---------------------------------------------------------------------------
// Scratch (device globals; runtime allocation forbidden)
// ---------------------------------------------------------------------------
__device__ __align__(256) __half g_xh [(size_t)B_ * D_];   // (x - mean) fp16
__device__ __align__(256) __half g_hh [(size_t)B_ * H_];   // h fp16 (pre/post LN, in-place)
__device__ __align__(256) __half g_qh [(size_t)B_ * K_];   // q_logits fp16
__device__ __align__(256) __half g_w1 [(size_t)H_ * D_];
__device__ __align__(256) __half g_w2 [(size_t)K_ * H_];
__device__ __align__(256) __half g_bt [(size_t)D_ * K_];

// ---------------------------------------------------------------------------
// Low-level helpers
// ---------------------------------------------------------------------------
__device__ __forceinline__ uint32_t smem_u32(const void* p) {
    uint32_t a;
    asm("{ .reg .u64 t; cvta.to.shared.u64 t, %1; cvt.u32.u64 %0, t; }"
        : "=r"(a) : "l"(p));
    return a;
}

__device__ __forceinline__ void cpa16(uint32_t dst, const void* src) {
    asm volatile("cp.async.cg.shared.global [%0], [%1], 16;"
                 :: "r"(dst), "l"(src) : "memory");
}
#define CP_COMMIT() asm volatile("cp.async.commit_group;" ::: "memory")
#define CP_WAIT1()  asm volatile("cp.async.wait_group 1;" ::: "memory")
#define CP_WAIT0()  asm volatile("cp.async.wait_group 0;" ::: "memory")

#define LDM_X4(r0, r1, r2, r3, addr)                                          \
    asm volatile("ldmatrix.sync.aligned.m8n8.x4.shared.b16 {%0,%1,%2,%3}, [%4];" \
                 : "=r"(r0), "=r"(r1), "=r"(r2), "=r"(r3) : "r"(addr))

__device__ __forceinline__ void mma_f16(float* c, const uint32_t* a,
                                        uint32_t b0, uint32_t b1) {
    asm volatile(
        "mma.sync.aligned.m16n8k16.row.col.f32.f16.f16.f32 "
        "{%0,%1,%2,%3}, {%4,%5,%6,%7}, {%8,%9}, {%0,%1,%2,%3};"
        : "+f"(c[0]), "+f"(c[1]), "+f"(c[2]), "+f"(c[3])
        : "r"(a[0]), "r"(a[1]), "r"(a[2]), "r"(a[3]), "r"(b0), "r"(b1));
}

// ---------------------------------------------------------------------------
// SMEM per stage: K-chunk 64 fp16 (128B/row), rows padded to 144B
// (bank stride 36 mod 32 = 4 -> conflict-free ldmatrix).
//   A[64][72]  @ 0     (9216 B)
//   B[128][72] @ 9216  (18432 B)
// Stage 27648 B, 3 stages = 82944 B -> 2 CTAs/SM.
// ---------------------------------------------------------------------------
#define ROWB   144
#define A_OFF  0
#define B_OFF  9216
#define STG    27648
#define SMEM_TOTAL (3 * STG)

#define NTHREADS 128

__device__ __forceinline__ void load_stage(uint32_t stb,
    const __half* __restrict__ A, const __half* __restrict__ Bw,
    int m0, int n0, int k0, int K, int tid)
{
    // A tile: 64 rows x 8 chunks(16B) = 512 chunks; 128 thr -> 4 iters
#pragma unroll
    for (int i = 0; i < 4; ++i) {
        const int idx = tid + i * NTHREADS;
        const int r = idx >> 3, c = idx & 7;
        cpa16(stb + A_OFF + (uint32_t)(r * ROWB + c * 16),
              A + (size_t)(m0 + r) * K + k0 + c * 8);
    }
    // B tile: 128 rows x 8 chunks = 1024 chunks; 8 iters
#pragma unroll
    for (int i = 0; i < 8; ++i) {
        const int idx = tid + i * NTHREADS;
        const int r = idx >> 3, c = idx & 7;
        cpa16(stb + B_OFF + (uint32_t)(r * ROWB + c * 16),
              Bw + (size_t)(n0 + r) * K + k0 + c * 8);
    }
}

// ---------------------------------------------------------------------------
// fp16 tensor-core GEMM. CTA tile 64(M)x128(N), 4 warps, warp tile 32x64.
// m16n8k16 HMMA, fp32 accum, register double-buffered fragments.
//   EPI 0: +bias -> fp16 Oh                       (GEMM1 -> h)
//   EPI 1: +bias -> C0,C1,C2 fp32 + fp16 Oh       (GEMM2 -> q)
//   EPI 2: sigmoid -> C0 fp32                     (GEMM3 -> x_recon)
// ---------------------------------------------------------------------------
template<int EPI>
__global__ void __launch_bounds__(NTHREADS, 2)
gemm_mma(const __half* __restrict__ A, const __half* __restrict__ Bw,
         const float* __restrict__ bias,
         float* __restrict__ C0, float* __restrict__ C1, float* __restrict__ C2,
         __half* __restrict__ Oh,
         int N, int K)
{
    extern __shared__ char smem[];
    const uint32_t sb = smem_u32(smem);

    const int tid  = threadIdx.x;
    const int lane = tid & 31;
    const int wid  = tid >> 5;       // 0..3
    const int wm   = wid & 1;        // 32-row slab
    const int wn   = wid >> 1;       // 64-col slab
    const int m0 = blockIdx.y * 64;
    const int n0 = blockIdx.x * 128;
    const int NC = K >> 6;

    const int lrow  = lane & 15;
    const int lcolb = ((lane >> 4) << 4);   // 0 or 16 bytes

    float acc[2][8][4];
#pragma unroll
    for (int m = 0; m < 2; ++m)
#pragma unroll
        for (int n = 0; n < 8; ++n)
#pragma unroll
            for (int j = 0; j < 4; ++j) acc[m][n][j] = 0.f;

    uint32_t afr[2][2][4], bfr[2][4][4];

    load_stage(sb,       A, Bw, m0, n0, 0,  K, tid); CP_COMMIT();
    load_stage(sb + STG, A, Bw, m0, n0, 64, K, tid); CP_COMMIT();

    uint32_t cur = 0;
    for (int c = 0; c < NC; ++c) {
        if (c + 1 < NC) CP_WAIT1(); else CP_WAIT0();
        __syncthreads();

        const uint32_t stb = sb + cur * STG;
        const uint32_t abase = stb + A_OFF + (wm * 32 + lrow) * ROWB + lcolb;
        const uint32_t bbase = stb + B_OFF + (wn * 64 + lrow) * ROWB + lcolb;

        // kk=0 fragments
#pragma unroll
        for (int mt = 0; mt < 2; ++mt)
            LDM_X4(afr[0][mt][0], afr[0][mt][1], afr[0][mt][2], afr[0][mt][3],
                   abase + mt * 16 * ROWB);
#pragma unroll
        for (int nt = 0; nt < 4; ++nt)
            LDM_X4(bfr[0][nt][0], bfr[0][nt][1], bfr[0][nt][2], bfr[0][nt][3],
                   bbase + nt * 16 * ROWB);

        // global prefetch of chunk c+2 (WAR-safe past the barrier)
        if (c + 2 < NC) {
            uint32_t ls = cur + 2; if (ls >= 3) ls -= 3;
            load_stage(sb + ls * STG, A, Bw, m0, n0, (c + 2) << 6, K, tid);
            CP_COMMIT();
        }

#pragma unroll
        for (int kk = 0; kk < 4; ++kk) {
            const int cb = kk & 1, nb = cb ^ 1;
            if (kk < 3) {
                const uint32_t ko = (kk + 1) * 32;
#pragma unroll
                for (int mt = 0; mt < 2; ++mt)
                    LDM_X4(afr[nb][mt][0], afr[nb][mt][1], afr[nb][mt][2],
                           afr[nb][mt][3], abase + mt * 16 * ROWB + ko);
#pragma unroll
                for (int nt = 0; nt < 4; ++nt)
                    LDM_X4(bfr[nb][nt][0], bfr[nb][nt][1], bfr[nb][nt][2],
                           bfr[nb][nt][3], bbase + nt * 16 * ROWB + ko);
            }
#pragma unroll
            for (int mt = 0; mt < 2; ++mt)
#pragma unroll
                for (int nt = 0; nt < 4; ++nt) {
                    mma_f16(acc[mt][2 * nt],     afr[cb][mt],
                            bfr[cb][nt][0], bfr[cb][nt][2]);
                    mma_f16(acc[mt][2 * nt + 1], afr[cb][mt],
                            bfr[cb][nt][1], bfr[cb][nt][3]);
                }
        }
        ++cur; if (cur == 3) cur = 0;
    }

    // ------------------------------ epilogue ------------------------------
    const int rbase = m0 + wm * 32 + (lane >> 2);
    const int cbase = n0 + wn * 64 + 2 * (lane & 3);
#pragma unroll
    for (int mt = 0; mt < 2; ++mt) {
        const int row = rbase + mt * 16;
#pragma unroll
        for (int n = 0; n < 8; ++n) {
            const int col = cbase + n * 8;
            float v[4] = {acc[mt][n][0], acc[mt][n][1], acc[mt][n][2], acc[mt][n][3]};
            if (EPI == 0 || EPI == 1) {
                const float bb0 = bias[col], bb1 = bias[col + 1];
                v[0] += bb0; v[1] += bb1; v[2] += bb0; v[3] += bb1;
            }
            if (EPI == 2) {
#pragma unroll
                for (int j = 0; j < 4; ++j) v[j] = 1.f / (1.f + __expf(-v[j]));
            }
            const size_t o0 = (size_t)row * N + col;
            const size_t o1 = (size_t)(row + 8) * N + col;
            if (EPI == 0) {
                *reinterpret_cast<__half2*>(Oh + o0) = __floats2half2_rn(v[0], v[1]);
                *reinterpret_cast<__half2*>(Oh + o1) = __floats2half2_rn(v[2], v[3]);
            } else {
                *reinterpret_cast<float2*>(C0 + o0) = make_float2(v[0], v[1]);
                *reinterpret_cast<float2*>(C0 + o1) = make_float2(v[2], v[3]);
                if (EPI == 1) {
                    *reinterpret_cast<float2*>(C1 + o0) = make_float2(v[0], v[1]);
                    *reinterpret_cast<float2*>(C1 + o1) = make_float2(v[2], v[3]);
                    *reinterpret_cast<float2*>(C2 + o0) = make_float2(v[0], v[1]);
                    *reinterpret_cast<float2*>(C2 + o1) = make_float2(v[2], v[3]);
                    *reinterpret_cast<__half2*>(Oh + o0) = __floats2half2_rn(v[0], v[1]);
                    *reinterpret_cast<__half2*>(Oh + o1) = __floats2half2_rn(v[2], v[3]);
                }
            }
        }
    }
}

// ---------------------------------------------------------------------------
// fp32 -> fp16 round (optional periodic mean subtraction, for x)
// ---------------------------------------------------------------------------
__global__ void __launch_bounds__(256)
cvt_kernel(const float* __restrict__ src, const float* __restrict__ mean,
           __half* __restrict__ hi, int dmask, int n4)
{
    int i = blockIdx.x * 256 + threadIdx.x;
    if (i >= n4) return;
    float4 v = reinterpret_cast<const float4*>(src)[i];
    int e = i * 4;
    if (mean) {
        v.x -= mean[(e + 0) & dmask]; v.y -= mean[(e + 1) & dmask];
        v.z -= mean[(e + 2) & dmask]; v.w -= mean[(e + 3) & dmask];
    }
    *reinterpret_cast<__half2*>(hi + e)     = __floats2half2_rn(v.x, v.y);
    *reinterpret_cast<__half2*>(hi + e + 2) = __floats2half2_rn(v.z, v.w);
}

// ---------------------------------------------------------------------------
// LayerNorm + ReLU over H, IN-PLACE on fp16 h. One block per row.
// 256 threads x 8 halfs (one uint4) each.
// ---------------------------------------------------------------------------
__global__ void __launch_bounds__(256)
ln_relu(__half* __restrict__ h, const float* __restrict__ w,
        const float* __restrict__ b)
{
    const int row = blockIdx.x;
    const int tid = threadIdx.x;
    uint4* hr = reinterpret_cast<uint4*>(h + (size_t)row * H_);

    uint4 raw = hr[tid];
    const __half2* hp = reinterpret_cast<const __half2*>(&raw);
    float f[8];
#pragma unroll
    for (int j = 0; j < 4; ++j) {
        float2 p = __half22float2(hp[j]);
        f[2 * j] = p.x; f[2 * j + 1] = p.y;
    }

    float s = 0.f, sq = 0.f;
#pragma unroll
    for (int j = 0; j < 8; ++j) { s += f[j]; sq += f[j] * f[j]; }
#pragma unroll
    for (int o = 16; o; o >>= 1) {
        s  += __shfl_xor_sync(0xffffffffu, s,  o);
        sq += __shfl_xor_sync(0xffffffffu, sq, o);
    }
    __shared__ float red[16];
    const int wd = tid >> 5, lane = tid & 31;
    if (lane == 0) { red[wd] = s; red[8 + wd] = sq; }
    __syncthreads();
    float ts = 0.f, tq = 0.f;
#pragma unroll
    for (int i = 0; i < 8; ++i) { ts += red[i]; tq += red[8 + i]; }

    const float mu  = ts * (1.f / H_);
    const float var = tq * (1.f / H_) - mu * mu;
    const float rr  = rsqrtf(var + LN_EPS);

    const int e0 = tid * 8;
    const float4 w0 = reinterpret_cast<const float4*>(w)[tid * 2];
    const float4 w1 = reinterpret_cast<const float4*>(w)[tid * 2 + 1];
    const float4 b0 = reinterpret_cast<const float4*>(b)[tid * 2];
    const float4 b1 = reinterpret_cast<const float4*>(b)[tid * 2 + 1];
    (void)e0;

    float o[8];
    o[0] = fmaxf((f[0] - mu) * rr * w0.x + b0.x, 0.f);
    o[1] = fmaxf((f[1] - mu) * rr * w0.y + b0.y, 0.f);
    o[2] = fmaxf((f[2] - mu) * rr * w0.z + b0.z, 0.f);
    o[3] = fmaxf((f[3] - mu) * rr * w0.w + b0.w, 0.f);
    o[4] = fmaxf((f[4] - mu) * rr * w1.x + b1.x, 0.f);
    o[5] = fmaxf((f[5] - mu) * rr * w1.y + b1.y, 0.f);
    o[6] = fmaxf((f[6] - mu) * rr * w1.z + b1.z, 0.f);
    o[7] = fmaxf((f[7] - mu) * rr * w1.w + b1.w, 0.f);

    uint4 outw;
    __half2* op = reinterpret_cast<__half2*>(&outw);
    op[0] = __floats2half2_rn(o[0], o[1]);
    op[1] = __floats2half2_rn(o[2], o[3]);
    op[2] = __floats2half2_rn(o[4], o[5]);
    op[3] = __floats2half2_rn(o[6], o[7]);
    hr[tid] = outw;
}

// ---------------------------------------------------------------------------
// kernel_launch  (GEMM1 at app-launch #4 -- the ncu capture slot)
// ---------------------------------------------------------------------------
extern "C" void kernel_launch(void* const* d_in, const int* in_sizes, int n_in,
                              void* d_out, int out_size)
{
    const float* x    = (const float*)d_in[0];
    const float* beta = (const float*)d_in[1];
    const float* mean = (const float*)d_in[2];
    const float* W1   = (const float*)d_in[3];
    const float* b1   = (const float*)d_in[4];
    const float* lnw  = (const float*)d_in[5];
    const float* lnb  = (const float*)d_in[6];
    const float* W2   = (const float*)d_in[7];
    const float* b2   = (const float*)d_in[8];

    float* out = (float*)d_out;
    float* q0 = out;                        // [B, K]
    float* xr = out + (size_t)B_ * K_;      // [B, D]
    float* q1 = xr + (size_t)B_ * D_;       // [B, K]
    float* q2 = q1 + (size_t)B_ * K_;       // [B, K]

    void *p_xh, *p_hh, *p_qh, *p_w1, *p_w2, *p_bt;
    cudaGetSymbolAddress(&p_xh, g_xh);
    cudaGetSymbolAddress(&p_hh, g_hh);
    cudaGetSymbolAddress(&p_qh, g_qh);
    cudaGetSymbolAddress(&p_w1, g_w1);
    cudaGetSymbolAddress(&p_w2, g_w2);
    cudaGetSymbolAddress(&p_bt, g_bt);

    __half *xh = (__half*)p_xh, *hh = (__half*)p_hh, *qh = (__half*)p_qh;
    __half *w1 = (__half*)p_w1, *w2 = (__half*)p_w2, *bt = (__half*)p_bt;

    cudaFuncSetAttribute(gemm_mma<0>, cudaFuncAttributeMaxDynamicSharedMemorySize, SMEM_TOTAL);
    cudaFuncSetAttribute(gemm_mma<1>, cudaFuncAttributeMaxDynamicSharedMemorySize, SMEM_TOTAL);
    cudaFuncSetAttribute(gemm_mma<2>, cudaFuncAttributeMaxDynamicSharedMemorySize, SMEM_TOTAL);

    // #1: x -> fp16 (with mean subtraction)
    cvt_kernel<<<(B_ * D_ / 4) / 256, 256>>>(x, mean, xh, D_ - 1, B_ * D_ / 4);
    // #2: W1 -> fp16
    cvt_kernel<<<(H_ * D_ / 4) / 256, 256>>>(W1, nullptr, w1, 0, H_ * D_ / 4);
    // #3: W2 -> fp16
    cvt_kernel<<<(K_ * H_ / 4) / 256, 256>>>(W2, nullptr, w2, 0, K_ * H_ / 4);

    // #4: GEMM1: h = (x-mean) @ W1^T + b1 -> fp16 hh   [8192, 2048], K=4096
    gemm_mma<0><<<dim3(H_ / 128, B_ / 64), NTHREADS, SMEM_TOTAL>>>(
        xh, w1, b1, nullptr, nullptr, nullptr, hh, H_, D_);

    // #5: beta -> fp16
    cvt_kernel<<<(D_ * K_ / 4) / 256, 256>>>(beta, nullptr, bt, 0, D_ * K_ / 4);

    // #6: LayerNorm + ReLU in place on fp16 hh
    ln_relu<<<B_, 256>>>(hh, lnw, lnb);

    // #7: GEMM2: q = h @ W2^T + b2   [8192, 512], K=2048 -> q0/q1/q2 + fp16 q
    gemm_mma<1><<<dim3(K_ / 128, B_ / 64), NTHREADS, SMEM_TOTAL>>>(
        hh, w2, b2, q0, q1, q2, qh, K_, H_);

    // #8: GEMM3: x_recon = sigmoid(q @ beta^T)   [8192, 4096], K=512
    gemm_mma<2><<<dim3(D_ / 128, B_ / 64), NTHREADS, SMEM_TOTAL>>>(
        qh, bt, nullptr, xr, nullptr, nullptr, nullptr, D_, K_);
}

// round 11
// speedup vs baseline: 1.1240x; 1.1240x over previous
#include <cuda_runtime.h>
#include <cuda_fp16.h>
#include <cstdint>

#define B_ 8192
#define D_ 4096
#define H_ 2048
#define K_ 512
#define LN_EPS 1e-5f

// ---------------------------------------------------------------------------
// Scratch (device globals; runtime allocation forbidden)
// ---------------------------------------------------------------------------
__device__ __align__(256) __half g_xh [(size_t)B_ * D_];   // (x - mean) fp16
__device__ __align__(256) __half g_hh [(size_t)B_ * H_];   // h fp16 (LN in-place)
__device__ __align__(256) __half g_qh [(size_t)B_ * K_];   // q_logits fp16
__device__ __align__(256) __half g_w1 [(size_t)H_ * D_];
__device__ __align__(256) __half g_w2 [(size_t)K_ * H_];
__device__ __align__(256) __half g_bt [(size_t)D_ * K_];

// ---------------------------------------------------------------------------
// Low-level helpers
// ---------------------------------------------------------------------------
__device__ __forceinline__ uint32_t smem_u32(const void* p) {
    uint32_t a;
    asm("{ .reg .u64 t; cvta.to.shared.u64 t, %1; cvt.u32.u64 %0, t; }"
        : "=r"(a) : "l"(p));
    return a;
}

__device__ __forceinline__ void cpa16(uint32_t dst, const void* src) {
    asm volatile("cp.async.cg.shared.global [%0], [%1], 16;"
                 :: "r"(dst), "l"(src) : "memory");
}
#define CP_COMMIT() asm volatile("cp.async.commit_group;" ::: "memory")
#define CP_WAIT1()  asm volatile("cp.async.wait_group 1;" ::: "memory")
#define CP_WAIT0()  asm volatile("cp.async.wait_group 0;" ::: "memory")

#define LDM_X4(r0, r1, r2, r3, addr)                                          \
    asm volatile("ldmatrix.sync.aligned.m8n8.x4.shared.b16 {%0,%1,%2,%3}, [%4];" \
                 : "=r"(r0), "=r"(r1), "=r"(r2), "=r"(r3) : "r"(addr))

__device__ __forceinline__ void mma_f16(float* c, const uint32_t* a,
                                        uint32_t b0, uint32_t b1) {
    asm volatile(
        "mma.sync.aligned.m16n8k16.row.col.f32.f16.f16.f32 "
        "{%0,%1,%2,%3}, {%4,%5,%6,%7}, {%8,%9}, {%0,%1,%2,%3};"
        : "+f"(c[0]), "+f"(c[1]), "+f"(c[2]), "+f"(c[3])
        : "r"(a[0]), "r"(a[1]), "r"(a[2]), "r"(a[3]), "r"(b0), "r"(b1));
}

// ---------------------------------------------------------------------------
// SMEM per stage: K-chunk 64 fp16 (128B/row), rows padded to 144B
// (bank stride 36 mod 32 = 4 -> conflict-free ldmatrix).
//   A[128][72] @ 0      (18432 B)
//   B[128][72] @ 18432
// Stage 36864 B, 3 stages = 110592 B -> 2 CTAs/SM.
// ---------------------------------------------------------------------------
#define ROWB   144
#define A_OFF  0
#define B_OFF  18432
#define STG    36864
#define SMEM_TOTAL (3 * STG)

#define NTHREADS 256

__device__ __forceinline__ void load_stage(uint32_t stb,
    const __half* __restrict__ A, const __half* __restrict__ Bw,
    int m0, int n0, int k0, int K, int tid)
{
#pragma unroll
    for (int i = 0; i < 4; ++i) {
        const int idx = tid + i * NTHREADS;
        const int r = idx >> 3;            // 0..127
        const int c = idx & 7;             // 16B chunk 0..7
        const size_t ga = (size_t)(m0 + r) * K + k0 + c * 8;
        const size_t gb = (size_t)(n0 + r) * K + k0 + c * 8;
        const uint32_t so = (uint32_t)(r * ROWB + c * 16);
        cpa16(stb + A_OFF + so, A + ga);
        cpa16(stb + B_OFF + so, Bw + gb);
    }
}

// ---------------------------------------------------------------------------
// Pure fp16 tensor-core GEMM (R7-proven config).
// CTA tile 128x128, 8 warps, warp tile 32x64, m16n8k16, fp32 accum,
// 3-stage cp.async pipeline with a single barrier per K-chunk.
//   EPI 0: +bias -> fp16 Oh                      (GEMM1 -> h)
//   EPI 1: +bias -> C0,C1,C2 fp32 + fp16 Oh      (GEMM2 -> q)
//   EPI 2: sigmoid -> C0 fp32                    (GEMM3 -> x_recon)
// ---------------------------------------------------------------------------
template<int EPI>
__global__ void __launch_bounds__(NTHREADS, 2)
gemm_mma(const __half* __restrict__ A, const __half* __restrict__ Bw,
         const float* __restrict__ bias,
         float* __restrict__ C0, float* __restrict__ C1, float* __restrict__ C2,
         __half* __restrict__ Oh,
         int N, int K)
{
    extern __shared__ char smem[];
    const uint32_t sb = smem_u32(smem);

    const int tid  = threadIdx.x;
    const int lane = tid & 31;
    const int wid  = tid >> 5;
    const int wm   = wid & 3;        // 32-row slab
    const int wn   = wid >> 2;       // 64-col slab
    const int m0 = blockIdx.y * 128;
    const int n0 = blockIdx.x * 128;
    const int NC = K >> 6;

    const int lrow  = lane & 15;
    const int lcolb = ((lane >> 4) << 4);   // 0 or 16 bytes

    float acc[2][8][4];
#pragma unroll
    for (int m = 0; m < 2; ++m)
#pragma unroll
        for (int n = 0; n < 8; ++n)
#pragma unroll
            for (int j = 0; j < 4; ++j) acc[m][n][j] = 0.f;

    // prologue: chunks 0,1 -> stages 0,1
    load_stage(sb,       A, Bw, m0, n0, 0,  K, tid); CP_COMMIT();
    load_stage(sb + STG, A, Bw, m0, n0, 64, K, tid); CP_COMMIT();

    uint32_t cur = 0;      // stage of chunk c
    for (int c = 0; c < NC; ++c) {
        if (c + 1 < NC) CP_WAIT1(); else CP_WAIT0();
        __syncthreads();   // single barrier: visibility + WAR protection

        // prefetch chunk c+2 into stage (cur+2)%3
        if (c + 2 < NC) {
            uint32_t ls = cur + 2; if (ls >= 3) ls -= 3;
            load_stage(sb + ls * STG, A, Bw, m0, n0, (c + 2) << 6, K, tid);
            CP_COMMIT();
        }

        const uint32_t stb = sb + cur * STG;
        const uint32_t abase = stb + A_OFF + (wm * 32 + lrow) * ROWB + lcolb;
        const uint32_t bbase = stb + B_OFF + (wn * 64 + lrow) * ROWB + lcolb;

#pragma unroll
        for (int kk = 0; kk < 4; ++kk) {
            const uint32_t ko = kk * 32;   // 16 elems = 32 bytes
            uint32_t a[2][4], b[4][4];
#pragma unroll
            for (int m = 0; m < 2; ++m) {
                const uint32_t ao = abase + m * 16 * ROWB + ko;
                LDM_X4(a[m][0], a[m][1], a[m][2], a[m][3], ao);
            }
#pragma unroll
            for (int nt = 0; nt < 4; ++nt) {
                const uint32_t bo = bbase + nt * 16 * ROWB + ko;
                LDM_X4(b[nt][0], b[nt][1], b[nt][2], b[nt][3], bo);
            }
#pragma unroll
            for (int m = 0; m < 2; ++m)
#pragma unroll
                for (int nt = 0; nt < 4; ++nt) {
                    mma_f16(acc[m][2 * nt],     a[m], b[nt][0], b[nt][2]);
                    mma_f16(acc[m][2 * nt + 1], a[m], b[nt][1], b[nt][3]);
                }
        }
        ++cur; if (cur == 3) cur = 0;
    }

    // ------------------------------ epilogue ------------------------------
    const int rbase = m0 + wm * 32 + (lane >> 2);
    const int cbase = n0 + wn * 64 + 2 * (lane & 3);
#pragma unroll
    for (int m = 0; m < 2; ++m) {
        const int row = rbase + m * 16;
#pragma unroll
        for (int n = 0; n < 8; ++n) {
            const int col = cbase + n * 8;
            float v[4] = {acc[m][n][0], acc[m][n][1], acc[m][n][2], acc[m][n][3]};
            if (EPI == 0 || EPI == 1) {
                const float bb0 = bias[col], bb1 = bias[col + 1];
                v[0] += bb0; v[1] += bb1; v[2] += bb0; v[3] += bb1;
            }
            if (EPI == 2) {
#pragma unroll
                for (int j = 0; j < 4; ++j) v[j] = 1.f / (1.f + __expf(-v[j]));
            }
            const size_t o0 = (size_t)row * N + col;
            const size_t o1 = (size_t)(row + 8) * N + col;
            if (EPI == 0) {
                // h written directly as fp16 (LN runs in place on it)
                *reinterpret_cast<__half2*>(Oh + o0) = __floats2half2_rn(v[0], v[1]);
                *reinterpret_cast<__half2*>(Oh + o1) = __floats2half2_rn(v[2], v[3]);
            } else {
                *reinterpret_cast<float2*>(C0 + o0) = make_float2(v[0], v[1]);
                *reinterpret_cast<float2*>(C0 + o1) = make_float2(v[2], v[3]);
                if (EPI == 1) {
                    *reinterpret_cast<float2*>(C1 + o0) = make_float2(v[0], v[1]);
                    *reinterpret_cast<float2*>(C1 + o1) = make_float2(v[2], v[3]);
                    *reinterpret_cast<float2*>(C2 + o0) = make_float2(v[0], v[1]);
                    *reinterpret_cast<float2*>(C2 + o1) = make_float2(v[2], v[3]);
                    *reinterpret_cast<__half2*>(Oh + o0) = __floats2half2_rn(v[0], v[1]);
                    *reinterpret_cast<__half2*>(Oh + o1) = __floats2half2_rn(v[2], v[3]);
                }
            }
        }
    }
}

// ---------------------------------------------------------------------------
// fp32 -> fp16 round (optional periodic mean subtraction, for x)
// ---------------------------------------------------------------------------
__global__ void __launch_bounds__(256)
cvt_kernel(const float* __restrict__ src, const float* __restrict__ mean,
           __half* __restrict__ hi, int dmask, int n4)
{
    int i = blockIdx.x * 256 + threadIdx.x;
    if (i >= n4) return;
    float4 v = reinterpret_cast<const float4*>(src)[i];
    int e = i * 4;
    if (mean) {
        v.x -= mean[(e + 0) & dmask]; v.y -= mean[(e + 1) & dmask];
        v.z -= mean[(e + 2) & dmask]; v.w -= mean[(e + 3) & dmask];
    }
    *reinterpret_cast<__half2*>(hi + e)     = __floats2half2_rn(v.x, v.y);
    *reinterpret_cast<__half2*>(hi + e + 2) = __floats2half2_rn(v.z, v.w);
}

// ---------------------------------------------------------------------------
// LayerNorm + ReLU over H, IN-PLACE on fp16 h. One block per row,
// 256 threads x 8 halfs (one uint4) each.
// ---------------------------------------------------------------------------
__global__ void __launch_bounds__(256)
ln_relu(__half* __restrict__ h, const float* __restrict__ w,
        const float* __restrict__ b)
{
    const int row = blockIdx.x;
    const int tid = threadIdx.x;
    uint4* hr = reinterpret_cast<uint4*>(h + (size_t)row * H_);

    uint4 raw = hr[tid];
    const __half2* hp = reinterpret_cast<const __half2*>(&raw);
    float f[8];
#pragma unroll
    for (int j = 0; j < 4; ++j) {
        float2 p = __half22float2(hp[j]);
        f[2 * j] = p.x; f[2 * j + 1] = p.y;
    }

    float s = 0.f, sq = 0.f;
#pragma unroll
    for (int j = 0; j < 8; ++j) { s += f[j]; sq += f[j] * f[j]; }
#pragma unroll
    for (int o = 16; o; o >>= 1) {
        s  += __shfl_xor_sync(0xffffffffu, s,  o);
        sq += __shfl_xor_sync(0xffffffffu, sq, o);
    }
    __shared__ float red[16];
    const int wd = tid >> 5, lane = tid & 31;
    if (lane == 0) { red[wd] = s; red[8 + wd] = sq; }
    __syncthreads();
    float ts = 0.f, tq = 0.f;
#pragma unroll
    for (int i = 0; i < 8; ++i) { ts += red[i]; tq += red[8 + i]; }

    const float mu  = ts * (1.f / H_);
    const float var = tq * (1.f / H_) - mu * mu;
    const float rr  = rsqrtf(var + LN_EPS);

    const float4 w0 = reinterpret_cast<const float4*>(w)[tid * 2];
    const float4 w1 = reinterpret_cast<const float4*>(w)[tid * 2 + 1];
    const float4 b0 = reinterpret_cast<const float4*>(b)[tid * 2];
    const float4 b1 = reinterpret_cast<const float4*>(b)[tid * 2 + 1];

    float o[8];
    o[0] = fmaxf((f[0] - mu) * rr * w0.x + b0.x, 0.f);
    o[1] = fmaxf((f[1] - mu) * rr * w0.y + b0.y, 0.f);
    o[2] = fmaxf((f[2] - mu) * rr * w0.z + b0.z, 0.f);
    o[3] = fmaxf((f[3] - mu) * rr * w0.w + b0.w, 0.f);
    o[4] = fmaxf((f[4] - mu) * rr * w1.x + b1.x, 0.f);
    o[5] = fmaxf((f[5] - mu) * rr * w1.y + b1.y, 0.f);
    o[6] = fmaxf((f[6] - mu) * rr * w1.z + b1.z, 0.f);
    o[7] = fmaxf((f[7] - mu) * rr * w1.w + b1.w, 0.f);

    uint4 outw;
    __half2* op = reinterpret_cast<__half2*>(&outw);
    op[0] = __floats2half2_rn(o[0], o[1]);
    op[1] = __floats2half2_rn(o[2], o[3]);
    op[2] = __floats2half2_rn(o[4], o[5]);
    op[3] = __floats2half2_rn(o[6], o[7]);
    hr[tid] = outw;
}

// ---------------------------------------------------------------------------
// kernel_launch  (GEMM1 at app-launch #4 -- the ncu capture slot)
// ---------------------------------------------------------------------------
extern "C" void kernel_launch(void* const* d_in, const int* in_sizes, int n_in,
                              void* d_out, int out_size)
{
    const float* x    = (const float*)d_in[0];
    const float* beta = (const float*)d_in[1];
    const float* mean = (const float*)d_in[2];
    const float* W1   = (const float*)d_in[3];
    const float* b1   = (const float*)d_in[4];
    const float* lnw  = (const float*)d_in[5];
    const float* lnb  = (const float*)d_in[6];
    const float* W2   = (const float*)d_in[7];
    const float* b2   = (const float*)d_in[8];

    float* out = (float*)d_out;
    float* q0 = out;                        // [B, K]
    float* xr = out + (size_t)B_ * K_;      // [B, D]
    float* q1 = xr + (size_t)B_ * D_;       // [B, K]
    float* q2 = q1 + (size_t)B_ * K_;       // [B, K]

    void *p_xh, *p_hh, *p_qh, *p_w1, *p_w2, *p_bt;
    cudaGetSymbolAddress(&p_xh, g_xh);
    cudaGetSymbolAddress(&p_hh, g_hh);
    cudaGetSymbolAddress(&p_qh, g_qh);
    cudaGetSymbolAddress(&p_w1, g_w1);
    cudaGetSymbolAddress(&p_w2, g_w2);
    cudaGetSymbolAddress(&p_bt, g_bt);

    __half *xh = (__half*)p_xh, *hh = (__half*)p_hh, *qh = (__half*)p_qh;
    __half *w1 = (__half*)p_w1, *w2 = (__half*)p_w2, *bt = (__half*)p_bt;

    cudaFuncSetAttribute(gemm_mma<0>, cudaFuncAttributeMaxDynamicSharedMemorySize, SMEM_TOTAL);
    cudaFuncSetAttribute(gemm_mma<1>, cudaFuncAttributeMaxDynamicSharedMemorySize, SMEM_TOTAL);
    cudaFuncSetAttribute(gemm_mma<2>, cudaFuncAttributeMaxDynamicSharedMemorySize, SMEM_TOTAL);

    // #1: x -> fp16 (with mean subtraction)
    cvt_kernel<<<(B_ * D_ / 4) / 256, 256>>>(x, mean, xh, D_ - 1, B_ * D_ / 4);
    // #2: W1 -> fp16
    cvt_kernel<<<(H_ * D_ / 4) / 256, 256>>>(W1, nullptr, w1, 0, H_ * D_ / 4);
    // #3: W2 -> fp16
    cvt_kernel<<<(K_ * H_ / 4) / 256, 256>>>(W2, nullptr, w2, 0, K_ * H_ / 4);

    // #4: GEMM1: h = (x-mean) @ W1^T + b1 -> fp16 hh   [8192, 2048], K=4096
    gemm_mma<0><<<dim3(H_ / 128, B_ / 128), NTHREADS, SMEM_TOTAL>>>(
        xh, w1, b1, nullptr, nullptr, nullptr, hh, H_, D_);

    // #5: beta -> fp16
    cvt_kernel<<<(D_ * K_ / 4) / 256, 256>>>(beta, nullptr, bt, 0, D_ * K_ / 4);

    // #6: LayerNorm + ReLU in place on fp16 hh
    ln_relu<<<B_, 256>>>(hh, lnw, lnb);

    // #7: GEMM2: q = h @ W2^T + b2   [8192, 512], K=2048 -> q0/q1/q2 + fp16 q
    gemm_mma<1><<<dim3(K_ / 128, B_ / 128), NTHREADS, SMEM_TOTAL>>>(
        hh, w2, b2, q0, q1, q2, qh, K_, H_);

    // #8: GEMM3: x_recon = sigmoid(q @ beta^T)   [8192, 4096], K=512
    gemm_mma<2><<<dim3(D_ / 128, B_ / 128), NTHREADS, SMEM_TOTAL>>>(
        qh, bt, nullptr, xr, nullptr, nullptr, nullptr, D_, K_);
}

// round 12
// speedup vs baseline: 1.1477x; 1.0211x over previous
#include <cuda_runtime.h>
#include <cuda_fp16.h>
#include <cstdint>

#define B_ 8192
#define D_ 4096
#define H_ 2048
#define K_ 512
#define LN_EPS 1e-5f

// ---------------------------------------------------------------------------
// Scratch (device globals; runtime allocation forbidden)
// ---------------------------------------------------------------------------
__device__ __align__(256) __half g_xh [(size_t)B_ * D_];   // (x - mean) fp16
__device__ __align__(256) __half g_hh [(size_t)B_ * H_];   // h fp16 (LN in-place)
__device__ __align__(256) __half g_qh [(size_t)B_ * K_];   // q_logits fp16
__device__ __align__(256) __half g_w1 [(size_t)H_ * D_];
__device__ __align__(256) __half g_w2 [(size_t)K_ * H_];
__device__ __align__(256) __half g_bt [(size_t)D_ * K_];

// ---------------------------------------------------------------------------
// Low-level helpers
// ---------------------------------------------------------------------------
__device__ __forceinline__ uint32_t smem_u32(const void* p) {
    uint32_t a;
    asm("{ .reg .u64 t; cvta.to.shared.u64 t, %1; cvt.u32.u64 %0, t; }"
        : "=r"(a) : "l"(p));
    return a;
}

__device__ __forceinline__ void cpa16(uint32_t dst, const void* src) {
    asm volatile("cp.async.cg.shared.global [%0], [%1], 16;"
                 :: "r"(dst), "l"(src) : "memory");
}
#define CP_COMMIT() asm volatile("cp.async.commit_group;" ::: "memory")
#define CP_WAIT1()  asm volatile("cp.async.wait_group 1;" ::: "memory")
#define CP_WAIT0()  asm volatile("cp.async.wait_group 0;" ::: "memory")

#define LDM_X4(r0, r1, r2, r3, addr)                                          \
    asm volatile("ldmatrix.sync.aligned.m8n8.x4.shared.b16 {%0,%1,%2,%3}, [%4];" \
                 : "=r"(r0), "=r"(r1), "=r"(r2), "=r"(r3) : "r"(addr))

__device__ __forceinline__ void mma_f16(float* c, const uint32_t* a,
                                        uint32_t b0, uint32_t b1) {
    asm volatile(
        "mma.sync.aligned.m16n8k16.row.col.f32.f16.f16.f32 "
        "{%0,%1,%2,%3}, {%4,%5,%6,%7}, {%8,%9}, {%0,%1,%2,%3};"
        : "+f"(c[0]), "+f"(c[1]), "+f"(c[2]), "+f"(c[3])
        : "r"(a[0]), "r"(a[1]), "r"(a[2]), "r"(a[3]), "r"(b0), "r"(b1));
}

// fast sigmoid: 0.5 * tanh(x/2) + 0.5   (single MUFU op vs EX2+RCP)
__device__ __forceinline__ float fast_sigmoid(float x) {
    float t;
    asm("tanh.approx.f32 %0, %1;" : "=f"(t) : "f"(x * 0.5f));
    return fmaf(0.5f, t, 0.5f);
}

// ---------------------------------------------------------------------------
// SMEM per stage: K-chunk 64 fp16 (128B/row), rows padded to 144B
// (bank stride 36 mod 32 = 4 -> conflict-free ldmatrix).
//   A[128][72] @ 0      (18432 B)
//   B[128][72] @ 18432
// Stage 36864 B, 3 stages = 110592 B -> 2 CTAs/SM.
// ---------------------------------------------------------------------------
#define ROWB   144
#define A_OFF  0
#define B_OFF  18432
#define STG    36864
#define SMEM_TOTAL (3 * STG)

#define NTHREADS 256

__device__ __forceinline__ void load_stage(uint32_t stb,
    const __half* __restrict__ A, const __half* __restrict__ Bw,
    int m0, int n0, int k0, int K, int tid)
{
#pragma unroll
    for (int i = 0; i < 4; ++i) {
        const int idx = tid + i * NTHREADS;
        const int r = idx >> 3;            // 0..127
        const int c = idx & 7;             // 16B chunk 0..7
        const size_t ga = (size_t)(m0 + r) * K + k0 + c * 8;
        const size_t gb = (size_t)(n0 + r) * K + k0 + c * 8;
        const uint32_t so = (uint32_t)(r * ROWB + c * 16);
        cpa16(stb + A_OFF + so, A + ga);
        cpa16(stb + B_OFF + so, Bw + gb);
    }
}

// ---------------------------------------------------------------------------
// Pure fp16 tensor-core GEMM (R7/R11-proven config).
// CTA tile 128x128, 8 warps, warp tile 32x64, m16n8k16, fp32 accum,
// 3-stage cp.async pipeline with a single barrier per K-chunk.
//   EPI 0: +bias -> fp16 Oh                      (GEMM1 -> h)
//   EPI 1: +bias -> C0,C1,C2 fp32 + fp16 Oh      (GEMM2 -> q)
//   EPI 2: sigmoid -> C0 fp32                    (GEMM3 -> x_recon)
// ---------------------------------------------------------------------------
template<int EPI>
__global__ void __launch_bounds__(NTHREADS, 2)
gemm_mma(const __half* __restrict__ A, const __half* __restrict__ Bw,
         const float* __restrict__ bias,
         float* __restrict__ C0, float* __restrict__ C1, float* __restrict__ C2,
         __half* __restrict__ Oh,
         int N, int K)
{
    extern __shared__ char smem[];
    const uint32_t sb = smem_u32(smem);

    const int tid  = threadIdx.x;
    const int lane = tid & 31;
    const int wid  = tid >> 5;
    const int wm   = wid & 3;        // 32-row slab
    const int wn   = wid >> 2;       // 64-col slab
    const int m0 = blockIdx.y * 128;
    const int n0 = blockIdx.x * 128;
    const int NC = K >> 6;

    const int lrow  = lane & 15;
    const int lcolb = ((lane >> 4) << 4);   // 0 or 16 bytes

    float acc[2][8][4];
#pragma unroll
    for (int m = 0; m < 2; ++m)
#pragma unroll
        for (int n = 0; n < 8; ++n)
#pragma unroll
            for (int j = 0; j < 4; ++j) acc[m][n][j] = 0.f;

    // prologue: chunks 0,1 -> stages 0,1
    load_stage(sb,       A, Bw, m0, n0, 0,  K, tid); CP_COMMIT();
    load_stage(sb + STG, A, Bw, m0, n0, 64, K, tid); CP_COMMIT();

    uint32_t cur = 0;      // stage of chunk c
    for (int c = 0; c < NC; ++c) {
        if (c + 1 < NC) CP_WAIT1(); else CP_WAIT0();
        __syncthreads();   // single barrier: visibility + WAR protection

        // prefetch chunk c+2 into stage (cur+2)%3
        if (c + 2 < NC) {
            uint32_t ls = cur + 2; if (ls >= 3) ls -= 3;
            load_stage(sb + ls * STG, A, Bw, m0, n0, (c + 2) << 6, K, tid);
            CP_COMMIT();
        }

        const uint32_t stb = sb + cur * STG;
        const uint32_t abase = stb + A_OFF + (wm * 32 + lrow) * ROWB + lcolb;
        const uint32_t bbase = stb + B_OFF + (wn * 64 + lrow) * ROWB + lcolb;

#pragma unroll
        for (int kk = 0; kk < 4; ++kk) {
            const uint32_t ko = kk * 32;   // 16 elems = 32 bytes
            uint32_t a[2][4], b[4][4];
#pragma unroll
            for (int m = 0; m < 2; ++m) {
                const uint32_t ao = abase + m * 16 * ROWB + ko;
                LDM_X4(a[m][0], a[m][1], a[m][2], a[m][3], ao);
            }
#pragma unroll
            for (int nt = 0; nt < 4; ++nt) {
                const uint32_t bo = bbase + nt * 16 * ROWB + ko;
                LDM_X4(b[nt][0], b[nt][1], b[nt][2], b[nt][3], bo);
            }
#pragma unroll
            for (int m = 0; m < 2; ++m)
#pragma unroll
                for (int nt = 0; nt < 4; ++nt) {
                    mma_f16(acc[m][2 * nt],     a[m], b[nt][0], b[nt][2]);
                    mma_f16(acc[m][2 * nt + 1], a[m], b[nt][1], b[nt][3]);
                }
        }
        ++cur; if (cur == 3) cur = 0;
    }

    // ------------------------------ epilogue ------------------------------
    const int rbase = m0 + wm * 32 + (lane >> 2);
    const int cbase = n0 + wn * 64 + 2 * (lane & 3);
#pragma unroll
    for (int m = 0; m < 2; ++m) {
        const int row = rbase + m * 16;
#pragma unroll
        for (int n = 0; n < 8; ++n) {
            const int col = cbase + n * 8;
            float v[4] = {acc[m][n][0], acc[m][n][1], acc[m][n][2], acc[m][n][3]};
            if (EPI == 0 || EPI == 1) {
                const float bb0 = bias[col], bb1 = bias[col + 1];
                v[0] += bb0; v[1] += bb1; v[2] += bb0; v[3] += bb1;
            }
            if (EPI == 2) {
#pragma unroll
                for (int j = 0; j < 4; ++j) v[j] = fast_sigmoid(v[j]);
            }
            const size_t o0 = (size_t)row * N + col;
            const size_t o1 = (size_t)(row + 8) * N + col;
            if (EPI == 0) {
                *reinterpret_cast<__half2*>(Oh + o0) = __floats2half2_rn(v[0], v[1]);
                *reinterpret_cast<__half2*>(Oh + o1) = __floats2half2_rn(v[2], v[3]);
            } else {
                *reinterpret_cast<float2*>(C0 + o0) = make_float2(v[0], v[1]);
                *reinterpret_cast<float2*>(C0 + o1) = make_float2(v[2], v[3]);
                if (EPI == 1) {
                    *reinterpret_cast<float2*>(C1 + o0) = make_float2(v[0], v[1]);
                    *reinterpret_cast<float2*>(C1 + o1) = make_float2(v[2], v[3]);
                    *reinterpret_cast<float2*>(C2 + o0) = make_float2(v[0], v[1]);
                    *reinterpret_cast<float2*>(C2 + o1) = make_float2(v[2], v[3]);
                    *reinterpret_cast<__half2*>(Oh + o0) = __floats2half2_rn(v[0], v[1]);
                    *reinterpret_cast<__half2*>(Oh + o1) = __floats2half2_rn(v[2], v[3]);
                }
            }
        }
    }
}

// ---------------------------------------------------------------------------
// Fused fp32 -> fp16 conversion of all four inputs in ONE launch.
// Block ranges: [0, XB) x (with mean), [XB, XB+W1B) W1, then W2, then beta.
// ---------------------------------------------------------------------------
#define XQ   (B_ * D_ / 4)     // 8388608 quads
#define W1Q  (H_ * D_ / 4)     // 2097152
#define W2Q  (K_ * H_ / 4)     //  262144
#define BTQ  (D_ * K_ / 4)     //  524288
#define XB   (XQ  / 256)       // 32768 blocks
#define W1B  (W1Q / 256)       //  8192
#define W2B  (W2Q / 256)       //  1024
#define BTB  (BTQ / 256)       //  2048

__global__ void __launch_bounds__(256)
cvt_all(const float* __restrict__ x,    const float* __restrict__ mean,
        __half* __restrict__ xh,
        const float* __restrict__ W1,   __half* __restrict__ w1,
        const float* __restrict__ W2,   __half* __restrict__ w2,
        const float* __restrict__ bt_in,__half* __restrict__ bt)
{
    const int bid = blockIdx.x;
    const int tid = threadIdx.x;
    const float* src; __half* dst; int q; bool with_mean = false;

    if (bid < XB)                { src = x;     dst = xh; q = bid * 256 + tid;              with_mean = true; }
    else if (bid < XB + W1B)     { src = W1;    dst = w1; q = (bid - XB) * 256 + tid; }
    else if (bid < XB + W1B + W2B){ src = W2;   dst = w2; q = (bid - XB - W1B) * 256 + tid; }
    else                         { src = bt_in; dst = bt; q = (bid - XB - W1B - W2B) * 256 + tid; }

    float4 v = reinterpret_cast<const float4*>(src)[q];
    const int e = q * 4;
    if (with_mean) {
        const int dmask = D_ - 1;
        v.x -= mean[(e + 0) & dmask]; v.y -= mean[(e + 1) & dmask];
        v.z -= mean[(e + 2) & dmask]; v.w -= mean[(e + 3) & dmask];
    }
    *reinterpret_cast<__half2*>(dst + e)     = __floats2half2_rn(v.x, v.y);
    *reinterpret_cast<__half2*>(dst + e + 2) = __floats2half2_rn(v.z, v.w);
}

// ---------------------------------------------------------------------------
// LayerNorm + ReLU over H, IN-PLACE on fp16 h. One block per row,
// 256 threads x 8 halfs (one uint4) each.
// ---------------------------------------------------------------------------
__global__ void __launch_bounds__(256)
ln_relu(__half* __restrict__ h, const float* __restrict__ w,
        const float* __restrict__ b)
{
    const int row = blockIdx.x;
    const int tid = threadIdx.x;
    uint4* hr = reinterpret_cast<uint4*>(h + (size_t)row * H_);

    uint4 raw = hr[tid];
    const __half2* hp = reinterpret_cast<const __half2*>(&raw);
    float f[8];
#pragma unroll
    for (int j = 0; j < 4; ++j) {
        float2 p = __half22float2(hp[j]);
        f[2 * j] = p.x; f[2 * j + 1] = p.y;
    }

    float s = 0.f, sq = 0.f;
#pragma unroll
    for (int j = 0; j < 8; ++j) { s += f[j]; sq += f[j] * f[j]; }
#pragma unroll
    for (int o = 16; o; o >>= 1) {
        s  += __shfl_xor_sync(0xffffffffu, s,  o);
        sq += __shfl_xor_sync(0xffffffffu, sq, o);
    }
    __shared__ float red[16];
    const int wd = tid >> 5, lane = tid & 31;
    if (lane == 0) { red[wd] = s; red[8 + wd] = sq; }
    __syncthreads();
    float ts = 0.f, tq = 0.f;
#pragma unroll
    for (int i = 0; i < 8; ++i) { ts += red[i]; tq += red[8 + i]; }

    const float mu  = ts * (1.f / H_);
    const float var = tq * (1.f / H_) - mu * mu;
    const float rr  = rsqrtf(var + LN_EPS);

    const float4 w0 = reinterpret_cast<const float4*>(w)[tid * 2];
    const float4 w1 = reinterpret_cast<const float4*>(w)[tid * 2 + 1];
    const float4 b0 = reinterpret_cast<const float4*>(b)[tid * 2];
    const float4 b1 = reinterpret_cast<const float4*>(b)[tid * 2 + 1];

    float o[8];
    o[0] = fmaxf((f[0] - mu) * rr * w0.x + b0.x, 0.f);
    o[1] = fmaxf((f[1] - mu) * rr * w0.y + b0.y, 0.f);
    o[2] = fmaxf((f[2] - mu) * rr * w0.z + b0.z, 0.f);
    o[3] = fmaxf((f[3] - mu) * rr * w0.w + b0.w, 0.f);
    o[4] = fmaxf((f[4] - mu) * rr * w1.x + b1.x, 0.f);
    o[5] = fmaxf((f[5] - mu) * rr * w1.y + b1.y, 0.f);
    o[6] = fmaxf((f[6] - mu) * rr * w1.z + b1.z, 0.f);
    o[7] = fmaxf((f[7] - mu) * rr * w1.w + b1.w, 0.f);

    uint4 outw;
    __half2* op = reinterpret_cast<__half2*>(&outw);
    op[0] = __floats2half2_rn(o[0], o[1]);
    op[1] = __floats2half2_rn(o[2], o[3]);
    op[2] = __floats2half2_rn(o[4], o[5]);
    op[3] = __floats2half2_rn(o[6], o[7]);
    hr[tid] = outw;
}

// ---------------------------------------------------------------------------
// kernel_launch
// ---------------------------------------------------------------------------
extern "C" void kernel_launch(void* const* d_in, const int* in_sizes, int n_in,
                              void* d_out, int out_size)
{
    const float* x    = (const float*)d_in[0];
    const float* beta = (const float*)d_in[1];
    const float* mean = (const float*)d_in[2];
    const float* W1   = (const float*)d_in[3];
    const float* b1   = (const float*)d_in[4];
    const float* lnw  = (const float*)d_in[5];
    const float* lnb  = (const float*)d_in[6];
    const float* W2   = (const float*)d_in[7];
    const float* b2   = (const float*)d_in[8];

    float* out = (float*)d_out;
    float* q0 = out;                        // [B, K]
    float* xr = out + (size_t)B_ * K_;      // [B, D]
    float* q1 = xr + (size_t)B_ * D_;       // [B, K]
    float* q2 = q1 + (size_t)B_ * K_;       // [B, K]

    void *p_xh, *p_hh, *p_qh, *p_w1, *p_w2, *p_bt;
    cudaGetSymbolAddress(&p_xh, g_xh);
    cudaGetSymbolAddress(&p_hh, g_hh);
    cudaGetSymbolAddress(&p_qh, g_qh);
    cudaGetSymbolAddress(&p_w1, g_w1);
    cudaGetSymbolAddress(&p_w2, g_w2);
    cudaGetSymbolAddress(&p_bt, g_bt);

    __half *xh = (__half*)p_xh, *hh = (__half*)p_hh, *qh = (__half*)p_qh;
    __half *w1 = (__half*)p_w1, *w2 = (__half*)p_w2, *bt = (__half*)p_bt;

    cudaFuncSetAttribute(gemm_mma<0>, cudaFuncAttributeMaxDynamicSharedMemorySize, SMEM_TOTAL);
    cudaFuncSetAttribute(gemm_mma<1>, cudaFuncAttributeMaxDynamicSharedMemorySize, SMEM_TOTAL);
    cudaFuncSetAttribute(gemm_mma<2>, cudaFuncAttributeMaxDynamicSharedMemorySize, SMEM_TOTAL);

    // #1: all fp32->fp16 conversions in one launch
    cvt_all<<<XB + W1B + W2B + BTB, 256>>>(x, mean, xh, W1, w1, W2, w2, beta, bt);

    // #2: GEMM1: h = (x-mean) @ W1^T + b1 -> fp16 hh   [8192, 2048], K=4096
    gemm_mma<0><<<dim3(H_ / 128, B_ / 128), NTHREADS, SMEM_TOTAL>>>(
        xh, w1, b1, nullptr, nullptr, nullptr, hh, H_, D_);

    // #3: LayerNorm + ReLU in place on fp16 hh
    ln_relu<<<B_, 256>>>(hh, lnw, lnb);

    // #4: GEMM2: q = h @ W2^T + b2   [8192, 512], K=2048 -> q0/q1/q2 + fp16 q
    gemm_mma<1><<<dim3(K_ / 128, B_ / 128), NTHREADS, SMEM_TOTAL>>>(
        hh, w2, b2, q0, q1, q2, qh, K_, H_);

    // #5: GEMM3: x_recon = sigmoid(q @ beta^T)   [8192, 4096], K=512
    gemm_mma<2><<<dim3(D_ / 128, B_ / 128), NTHREADS, SMEM_TOTAL>>>(
        qh, bt, nullptr, xr, nullptr, nullptr, nullptr, D_, K_);
}

// round 13
// speedup vs baseline: 1.1581x; 1.0091x over previous
#include <cuda_runtime.h>
#include <cuda_fp16.h>
#include <cstdint>

#define B_ 8192
#define D_ 4096
#define H_ 2048
#define K_ 512
#define LN_EPS 1e-5f

// ---------------------------------------------------------------------------
// Scratch (device globals; runtime allocation forbidden)
// ---------------------------------------------------------------------------
__device__ __align__(256) __half g_xh [(size_t)B_ * D_];   // (x - mean) fp16
__device__ __align__(256) __half g_hh [(size_t)B_ * H_];   // h fp16 (LN in-place)
__device__ __align__(256) __half g_qh [(size_t)B_ * K_];   // q_logits fp16
__device__ __align__(256) __half g_w1 [(size_t)H_ * D_];
__device__ __align__(256) __half g_w2 [(size_t)K_ * H_];
__device__ __align__(256) __half g_bt [(size_t)D_ * K_];

// ---------------------------------------------------------------------------
// Low-level helpers
// ---------------------------------------------------------------------------
__device__ __forceinline__ uint32_t smem_u32(const void* p) {
    uint32_t a;
    asm("{ .reg .u64 t; cvta.to.shared.u64 t, %1; cvt.u32.u64 %0, t; }"
        : "=r"(a) : "l"(p));
    return a;
}

__device__ __forceinline__ void cpa16(uint32_t dst, const void* src) {
    asm volatile("cp.async.cg.shared.global [%0], [%1], 16;"
                 :: "r"(dst), "l"(src) : "memory");
}
#define CP_COMMIT() asm volatile("cp.async.commit_group;" ::: "memory")
#define CP_WAIT1()  asm volatile("cp.async.wait_group 1;" ::: "memory")
#define CP_WAIT0()  asm volatile("cp.async.wait_group 0;" ::: "memory")

#define LDM_X4(r0, r1, r2, r3, addr)                                          \
    asm volatile("ldmatrix.sync.aligned.m8n8.x4.shared.b16 {%0,%1,%2,%3}, [%4];" \
                 : "=r"(r0), "=r"(r1), "=r"(r2), "=r"(r3) : "r"(addr))

__device__ __forceinline__ void mma_f16(float* c, const uint32_t* a,
                                        uint32_t b0, uint32_t b1) {
    asm volatile(
        "mma.sync.aligned.m16n8k16.row.col.f32.f16.f16.f32 "
        "{%0,%1,%2,%3}, {%4,%5,%6,%7}, {%8,%9}, {%0,%1,%2,%3};"
        : "+f"(c[0]), "+f"(c[1]), "+f"(c[2]), "+f"(c[3])
        : "r"(a[0]), "r"(a[1]), "r"(a[2]), "r"(a[3]), "r"(b0), "r"(b1));
}

// fast sigmoid: 0.5 * tanh(x/2) + 0.5   (single MUFU op vs EX2+RCP)
__device__ __forceinline__ float fast_sigmoid(float x) {
    float t;
    asm("tanh.approx.f32 %0, %1;" : "=f"(t) : "f"(x * 0.5f));
    return fmaf(0.5f, t, 0.5f);
}

// ---------------------------------------------------------------------------
// SMEM per stage: K-chunk 64 fp16 (128B/row), rows padded to 144B
// (bank stride 36 mod 32 = 4 -> conflict-free ldmatrix).
//   A[128][72] @ 0      (18432 B)
//   B[128][72] @ 18432
// Stage 36864 B, 3 stages = 110592 B -> 2 CTAs/SM.
// ---------------------------------------------------------------------------
#define ROWB   144
#define A_OFF  0
#define B_OFF  18432
#define STG    36864
#define SMEM_TOTAL (3 * STG)

#define NTHREADS 256

__device__ __forceinline__ void load_stage(uint32_t stb,
    const __half* __restrict__ A, const __half* __restrict__ Bw,
    int m0, int n0, int k0, int K, int tid)
{
#pragma unroll
    for (int i = 0; i < 4; ++i) {
        const int idx = tid + i * NTHREADS;
        const int r = idx >> 3;            // 0..127
        const int c = idx & 7;             // 16B chunk 0..7
        const size_t ga = (size_t)(m0 + r) * K + k0 + c * 8;
        const size_t gb = (size_t)(n0 + r) * K + k0 + c * 8;
        const uint32_t so = (uint32_t)(r * ROWB + c * 16);
        cpa16(stb + A_OFF + so, A + ga);
        cpa16(stb + B_OFF + so, Bw + gb);
    }
}

// ---------------------------------------------------------------------------
// Pure fp16 tensor-core GEMM (proven config).
// CTA tile 128x128, 8 warps, warp tile 32x64, m16n8k16, fp32 accum,
// 3-stage cp.async pipeline with a single barrier per K-chunk.
//   EPI 0: +bias -> fp16 Oh                      (GEMM1 -> h)
//   EPI 1: +bias -> C0,C1,C2 fp32 + fp16 Oh      (GEMM2 -> q)
//   EPI 2: sigmoid -> C0 fp32                    (GEMM3 -> x_recon)
// ---------------------------------------------------------------------------
template<int EPI>
__global__ void __launch_bounds__(NTHREADS, 2)
gemm_mma(const __half* __restrict__ A, const __half* __restrict__ Bw,
         const float* __restrict__ bias,
         float* __restrict__ C0, float* __restrict__ C1, float* __restrict__ C2,
         __half* __restrict__ Oh,
         int N, int K)
{
    extern __shared__ char smem[];
    const uint32_t sb = smem_u32(smem);

    const int tid  = threadIdx.x;
    const int lane = tid & 31;
    const int wid  = tid >> 5;
    const int wm   = wid & 3;        // 32-row slab
    const int wn   = wid >> 2;       // 64-col slab
    const int m0 = blockIdx.y * 128;
    const int n0 = blockIdx.x * 128;
    const int NC = K >> 6;

    const int lrow  = lane & 15;
    const int lcolb = ((lane >> 4) << 4);   // 0 or 16 bytes

    float acc[2][8][4];
#pragma unroll
    for (int m = 0; m < 2; ++m)
#pragma unroll
        for (int n = 0; n < 8; ++n)
#pragma unroll
            for (int j = 0; j < 4; ++j) acc[m][n][j] = 0.f;

    // prologue: chunks 0,1 -> stages 0,1
    load_stage(sb,       A, Bw, m0, n0, 0,  K, tid); CP_COMMIT();
    load_stage(sb + STG, A, Bw, m0, n0, 64, K, tid); CP_COMMIT();

    uint32_t cur = 0;      // stage of chunk c
    for (int c = 0; c < NC; ++c) {
        if (c + 1 < NC) CP_WAIT1(); else CP_WAIT0();
        __syncthreads();   // single barrier: visibility + WAR protection

        // prefetch chunk c+2 into stage (cur+2)%3
        if (c + 2 < NC) {
            uint32_t ls = cur + 2; if (ls >= 3) ls -= 3;
            load_stage(sb + ls * STG, A, Bw, m0, n0, (c + 2) << 6, K, tid);
            CP_COMMIT();
        }

        const uint32_t stb = sb + cur * STG;
        const uint32_t abase = stb + A_OFF + (wm * 32 + lrow) * ROWB + lcolb;
        const uint32_t bbase = stb + B_OFF + (wn * 64 + lrow) * ROWB + lcolb;

#pragma unroll
        for (int kk = 0; kk < 4; ++kk) {
            const uint32_t ko = kk * 32;   // 16 elems = 32 bytes
            uint32_t a[2][4], b[4][4];
#pragma unroll
            for (int m = 0; m < 2; ++m) {
                const uint32_t ao = abase + m * 16 * ROWB + ko;
                LDM_X4(a[m][0], a[m][1], a[m][2], a[m][3], ao);
            }
#pragma unroll
            for (int nt = 0; nt < 4; ++nt) {
                const uint32_t bo = bbase + nt * 16 * ROWB + ko;
                LDM_X4(b[nt][0], b[nt][1], b[nt][2], b[nt][3], bo);
            }
#pragma unroll
            for (int m = 0; m < 2; ++m)
#pragma unroll
                for (int nt = 0; nt < 4; ++nt) {
                    mma_f16(acc[m][2 * nt],     a[m], b[nt][0], b[nt][2]);
                    mma_f16(acc[m][2 * nt + 1], a[m], b[nt][1], b[nt][3]);
                }
        }
        ++cur; if (cur == 3) cur = 0;
    }

    // ------------------------------ epilogue ------------------------------
    const int rbase = m0 + wm * 32 + (lane >> 2);
    const int cbase = n0 + wn * 64 + 2 * (lane & 3);
#pragma unroll
    for (int m = 0; m < 2; ++m) {
        const int row = rbase + m * 16;
#pragma unroll
        for (int n = 0; n < 8; ++n) {
            const int col = cbase + n * 8;
            float v[4] = {acc[m][n][0], acc[m][n][1], acc[m][n][2], acc[m][n][3]};
            if (EPI == 0 || EPI == 1) {
                const float bb0 = bias[col], bb1 = bias[col + 1];
                v[0] += bb0; v[1] += bb1; v[2] += bb0; v[3] += bb1;
            }
            if (EPI == 2) {
#pragma unroll
                for (int j = 0; j < 4; ++j) v[j] = fast_sigmoid(v[j]);
            }
            const size_t o0 = (size_t)row * N + col;
            const size_t o1 = (size_t)(row + 8) * N + col;
            if (EPI == 0) {
                *reinterpret_cast<__half2*>(Oh + o0) = __floats2half2_rn(v[0], v[1]);
                *reinterpret_cast<__half2*>(Oh + o1) = __floats2half2_rn(v[2], v[3]);
            } else {
                *reinterpret_cast<float2*>(C0 + o0) = make_float2(v[0], v[1]);
                *reinterpret_cast<float2*>(C0 + o1) = make_float2(v[2], v[3]);
                if (EPI == 1) {
                    *reinterpret_cast<float2*>(C1 + o0) = make_float2(v[0], v[1]);
                    *reinterpret_cast<float2*>(C1 + o1) = make_float2(v[2], v[3]);
                    *reinterpret_cast<float2*>(C2 + o0) = make_float2(v[0], v[1]);
                    *reinterpret_cast<float2*>(C2 + o1) = make_float2(v[2], v[3]);
                    *reinterpret_cast<__half2*>(Oh + o0) = __floats2half2_rn(v[0], v[1]);
                    *reinterpret_cast<__half2*>(Oh + o1) = __floats2half2_rn(v[2], v[3]);
                }
            }
        }
    }
}

// ---------------------------------------------------------------------------
// Fused fp32 -> fp16 conversion of all four inputs in ONE launch, with
// 4 independent float4 loads per thread (MLP=4 -> latency fully overlapped).
// Each block covers 1024 quads (256 threads x 4 quads, stride 256).
// ---------------------------------------------------------------------------
#define XQ    (B_ * D_ / 4)     // 8388608 quads
#define W1Q   (H_ * D_ / 4)     // 2097152
#define W2Q   (K_ * H_ / 4)     //  262144
#define BTQ   (D_ * K_ / 4)     //  524288
#define XBLK  (XQ  / 1024)      // 8192 blocks
#define W1BLK (W1Q / 1024)      // 2048
#define W2BLK (W2Q / 1024)      //  256
#define BTBLK (BTQ / 1024)      //  512

__global__ void __launch_bounds__(256)
cvt_all(const float* __restrict__ x,    const float* __restrict__ mean,
        __half* __restrict__ xh,
        const float* __restrict__ W1,   __half* __restrict__ w1,
        const float* __restrict__ W2,   __half* __restrict__ w2,
        const float* __restrict__ bt_in,__half* __restrict__ bt)
{
    const int bid = blockIdx.x;
    const int tid = threadIdx.x;
    const float* src; __half* dst; int qb; bool with_mean = false;

    if (bid < XBLK) {
        src = x; dst = xh; qb = bid * 1024 + tid; with_mean = true;
    } else if (bid < XBLK + W1BLK) {
        src = W1; dst = w1; qb = (bid - XBLK) * 1024 + tid;
    } else if (bid < XBLK + W1BLK + W2BLK) {
        src = W2; dst = w2; qb = (bid - XBLK - W1BLK) * 1024 + tid;
    } else {
        src = bt_in; dst = bt; qb = (bid - XBLK - W1BLK - W2BLK) * 1024 + tid;
    }

    // 4 independent loads (addresses strided by 256 quads)
    float4 v[4];
#pragma unroll
    for (int k = 0; k < 4; ++k)
        v[k] = reinterpret_cast<const float4*>(src)[qb + k * 256];

    if (with_mean) {
        const int dmask = D_ - 1;
#pragma unroll
        for (int k = 0; k < 4; ++k) {
            const int e = (qb + k * 256) * 4;
            v[k].x -= mean[(e + 0) & dmask]; v[k].y -= mean[(e + 1) & dmask];
            v[k].z -= mean[(e + 2) & dmask]; v[k].w -= mean[(e + 3) & dmask];
        }
    }

#pragma unroll
    for (int k = 0; k < 4; ++k) {
        const int e = (qb + k * 256) * 4;
        *reinterpret_cast<__half2*>(dst + e)     = __floats2half2_rn(v[k].x, v[k].y);
        *reinterpret_cast<__half2*>(dst + e + 2) = __floats2half2_rn(v[k].z, v[k].w);
    }
}

// ---------------------------------------------------------------------------
// LayerNorm + ReLU over H, IN-PLACE on fp16 h. One block per row,
// 256 threads x 8 halfs (one uint4) each.
// ---------------------------------------------------------------------------
__global__ void __launch_bounds__(256)
ln_relu(__half* __restrict__ h, const float* __restrict__ w,
        const float* __restrict__ b)
{
    const int row = blockIdx.x;
    const int tid = threadIdx.x;
    uint4* hr = reinterpret_cast<uint4*>(h + (size_t)row * H_);

    uint4 raw = hr[tid];
    const __half2* hp = reinterpret_cast<const __half2*>(&raw);
    float f[8];
#pragma unroll
    for (int j = 0; j < 4; ++j) {
        float2 p = __half22float2(hp[j]);
        f[2 * j] = p.x; f[2 * j + 1] = p.y;
    }

    float s = 0.f, sq = 0.f;
#pragma unroll
    for (int j = 0; j < 8; ++j) { s += f[j]; sq += f[j] * f[j]; }
#pragma unroll
    for (int o = 16; o; o >>= 1) {
        s  += __shfl_xor_sync(0xffffffffu, s,  o);
        sq += __shfl_xor_sync(0xffffffffu, sq, o);
    }
    __shared__ float red[16];
    const int wd = tid >> 5, lane = tid & 31;
    if (lane == 0) { red[wd] = s; red[8 + wd] = sq; }
    __syncthreads();
    float ts = 0.f, tq = 0.f;
#pragma unroll
    for (int i = 0; i < 8; ++i) { ts += red[i]; tq += red[8 + i]; }

    const float mu  = ts * (1.f / H_);
    const float var = tq * (1.f / H_) - mu * mu;
    const float rr  = rsqrtf(var + LN_EPS);

    const float4 w0 = reinterpret_cast<const float4*>(w)[tid * 2];
    const float4 w1 = reinterpret_cast<const float4*>(w)[tid * 2 + 1];
    const float4 b0 = reinterpret_cast<const float4*>(b)[tid * 2];
    const float4 b1 = reinterpret_cast<const float4*>(b)[tid * 2 + 1];

    float o[8];
    o[0] = fmaxf((f[0] - mu) * rr * w0.x + b0.x, 0.f);
    o[1] = fmaxf((f[1] - mu) * rr * w0.y + b0.y, 0.f);
    o[2] = fmaxf((f[2] - mu) * rr * w0.z + b0.z, 0.f);
    o[3] = fmaxf((f[3] - mu) * rr * w0.w + b0.w, 0.f);
    o[4] = fmaxf((f[4] - mu) * rr * w1.x + b1.x, 0.f);
    o[5] = fmaxf((f[5] - mu) * rr * w1.y + b1.y, 0.f);
    o[6] = fmaxf((f[6] - mu) * rr * w1.z + b1.z, 0.f);
    o[7] = fmaxf((f[7] - mu) * rr * w1.w + b1.w, 0.f);

    uint4 outw;
    __half2* op = reinterpret_cast<__half2*>(&outw);
    op[0] = __floats2half2_rn(o[0], o[1]);
    op[1] = __floats2half2_rn(o[2], o[3]);
    op[2] = __floats2half2_rn(o[4], o[5]);
    op[3] = __floats2half2_rn(o[6], o[7]);
    hr[tid] = outw;
}

// ---------------------------------------------------------------------------
// kernel_launch
// ---------------------------------------------------------------------------
extern "C" void kernel_launch(void* const* d_in, const int* in_sizes, int n_in,
                              void* d_out, int out_size)
{
    const float* x    = (const float*)d_in[0];
    const float* beta = (const float*)d_in[1];
    const float* mean = (const float*)d_in[2];
    const float* W1   = (const float*)d_in[3];
    const float* b1   = (const float*)d_in[4];
    const float* lnw  = (const float*)d_in[5];
    const float* lnb  = (const float*)d_in[6];
    const float* W2   = (const float*)d_in[7];
    const float* b2   = (const float*)d_in[8];

    float* out = (float*)d_out;
    float* q0 = out;                        // [B, K]
    float* xr = out + (size_t)B_ * K_;      // [B, D]
    float* q1 = xr + (size_t)B_ * D_;       // [B, K]
    float* q2 = q1 + (size_t)B_ * K_;       // [B, K]

    void *p_xh, *p_hh, *p_qh, *p_w1, *p_w2, *p_bt;
    cudaGetSymbolAddress(&p_xh, g_xh);
    cudaGetSymbolAddress(&p_hh, g_hh);
    cudaGetSymbolAddress(&p_qh, g_qh);
    cudaGetSymbolAddress(&p_w1, g_w1);
    cudaGetSymbolAddress(&p_w2, g_w2);
    cudaGetSymbolAddress(&p_bt, g_bt);

    __half *xh = (__half*)p_xh, *hh = (__half*)p_hh, *qh = (__half*)p_qh;
    __half *w1 = (__half*)p_w1, *w2 = (__half*)p_w2, *bt = (__half*)p_bt;

    cudaFuncSetAttribute(gemm_mma<0>, cudaFuncAttributeMaxDynamicSharedMemorySize, SMEM_TOTAL);
    cudaFuncSetAttribute(gemm_mma<1>, cudaFuncAttributeMaxDynamicSharedMemorySize, SMEM_TOTAL);
    cudaFuncSetAttribute(gemm_mma<2>, cudaFuncAttributeMaxDynamicSharedMemorySize, SMEM_TOTAL);

    // #1: all fp32->fp16 conversions in one launch (MLP=4)
    cvt_all<<<XBLK + W1BLK + W2BLK + BTBLK, 256>>>(x, mean, xh, W1, w1, W2, w2, beta, bt);

    // #2: GEMM1: h = (x-mean) @ W1^T + b1 -> fp16 hh   [8192, 2048], K=4096
    gemm_mma<0><<<dim3(H_ / 128, B_ / 128), NTHREADS, SMEM_TOTAL>>>(
        xh, w1, b1, nullptr, nullptr, nullptr, hh, H_, D_);

    // #3: LayerNorm + ReLU in place on fp16 hh
    ln_relu<<<B_, 256>>>(hh, lnw, lnb);

    // #4: GEMM2: q = h @ W2^T + b2   [8192, 512], K=2048 -> q0/q1/q2 + fp16 q
    gemm_mma<1><<<dim3(K_ / 128, B_ / 128), NTHREADS, SMEM_TOTAL>>>(
        hh, w2, b2, q0, q1, q2, qh, K_, H_);

    // #5: GEMM3: x_recon = sigmoid(q @ beta^T)   [8192, 4096], K=512
    gemm_mma<2><<<dim3(D_ / 128, B_ / 128), NTHREADS, SMEM_TOTAL>>>(
        qh, bt, nullptr, xr, nullptr, nullptr, nullptr, D_, K_);
}